// round 6
// baseline (speedup 1.0000x reference)
#include <cuda_runtime.h>

#define IC 1152
#define OC 10
#define ID 8
#define OD 16
#define OD2 8          // packed f32x2 pairs
#define BATCH 32
#define NITER 5
#define EPSV 1e-20f
#define ICPB 4
#define NTHREADS 320   // 10 warps: warp = oc, lane = b
#define WSLAB (OC * ID * OD)   // 1280 floats per ic

typedef unsigned long long u64;

__device__ __forceinline__ u64 pk2(float lo, float hi) {
    u64 r; asm("mov.b64 %0, {%1,%2};" : "=l"(r) : "f"(lo), "f"(hi)); return r;
}
__device__ __forceinline__ float2 upk2(u64 v) {
    float2 f; asm("mov.b64 {%0,%1}, %2;" : "=f"(f.x), "=f"(f.y) : "l"(v)); return f;
}
__device__ __forceinline__ u64 mul2(u64 a, u64 b) {
    u64 r; asm("mul.rn.f32x2 %0, %1, %2;" : "=l"(r) : "l"(a), "l"(b)); return r;
}
__device__ __forceinline__ u64 add2(u64 a, u64 b) {
    u64 r; asm("add.rn.f32x2 %0, %1, %2;" : "=l"(r) : "l"(a), "l"(b)); return r;
}
__device__ __forceinline__ u64 fma2(u64 a, u64 b, u64 c) {
    u64 r; asm("fma.rn.f32x2 %0, %1, %2, %3;" : "=l"(r) : "l"(a), "l"(b), "l"(c)); return r;
}

__global__ void zero_out_kernel(float* out, int n) {
    int i = blockIdx.x * blockDim.x + threadIdx.x;
    if (i < n) out[i] = 0.0f;
}

__global__ __launch_bounds__(NTHREADS, 2)
void caps_kernel(const float* __restrict__ x,
                 const float* __restrict__ w,
                 float* __restrict__ out) {
    __shared__ __align__(16) float w_s[WSLAB];      // current ic weight slab
    __shared__ float x_s[BATCH][ID + 1];            // padded: stride 9
    __shared__ float alpha_s[BATCH][OC];

    const int tid = threadIdx.x;
    const int b   = tid & 31;     // lane
    const int oc  = tid >> 5;     // warp

    // ---- load slab 0 ----
    {
        const int ic0 = blockIdx.x * ICPB;
        for (int i = tid; i < WSLAB; i += NTHREADS)
            w_s[i] = w[ic0 * WSLAB + i];
        if (tid < BATCH * ID) {
            int bb = tid >> 3, id = tid & 7;
            x_s[bb][id] = x[(bb * IC + ic0) * ID + id];
        }
    }
    __syncthreads();

    for (int k = 0; k < ICPB; k++) {
        // ---- normalize x over ID ----
        float xn[ID];
        float xs = 0.0f;
#pragma unroll
        for (int id = 0; id < ID; id++) { xn[id] = x_s[b][id]; xs += xn[id]; }
        float xr = __fdividef(1.0f, xs + EPSV);
#pragma unroll
        for (int id = 0; id < ID; id++) xn[id] *= xr;

        const u64* wq = reinterpret_cast<const u64*>(w_s + oc * ID * OD);

        // ---- NNMF, factored form:
        //   d[id] = Σ_j outv[j]·w[id][j]      8 independent packed-dot chains
        //   s[id] = xn[id] / (d[id]+ε)        8 overlapping MUFU rcps
        //   t[j] += s[id]·w[id][j]            8 independent column chains
        //   outv[j] *= t[j]
        // per-iteration normalization is scale-invariant; applied once ----
        u64 outv2[OD2];
#pragma unroll
        for (int j = 0; j < OD2; j++) outv2[j] = pk2(1.0f / OD, 1.0f / OD);

#pragma unroll
        for (int it = 0; it < NITER; it++) {
            // phase 1: dots, scalar results (8 regs)
            float s[ID];
#pragma unroll
            for (int id = 0; id < ID; id++) {
                u64 acc = mul2(outv2[0], wq[id * OD2 + 0]);
#pragma unroll
                for (int j = 1; j < OD2; j++)
                    acc = fma2(outv2[j], wq[id * OD2 + j], acc);
                float2 f = upk2(acc);
                s[id] = f.x + f.y;
            }
            // phase 2: batched reciprocals
#pragma unroll
            for (int id = 0; id < ID; id++)
                s[id] = __fdividef(xn[id], s[id] + EPSV);
            // phase 3: column accumulation, 8 independent chains
            u64 t[OD2];
            {
                u64 sp = pk2(s[0], s[0]);
#pragma unroll
                for (int j = 0; j < OD2; j++) t[j] = mul2(sp, wq[j]);
            }
#pragma unroll
            for (int id = 1; id < ID; id++) {
                u64 sp = pk2(s[id], s[id]);
#pragma unroll
                for (int j = 0; j < OD2; j++)
                    t[j] = fma2(sp, wq[id * OD2 + j], t[j]);
            }
#pragma unroll
            for (int j = 0; j < OD2; j++)
                outv2[j] = mul2(outv2[j], t[j]);
        }

        // ---- final normalization over OD (needed before alpha mixes oc) ----
        {
            u64 t01 = add2(outv2[0], outv2[1]), t23 = add2(outv2[2], outv2[3]);
            u64 t45 = add2(outv2[4], outv2[5]), t67 = add2(outv2[6], outv2[7]);
            float2 tf = upk2(add2(add2(t01, t23), add2(t45, t67)));
            float rn = __fdividef(1.0f, tf.x + tf.y + EPSV);
            u64 rn2 = pk2(rn, rn);
#pragma unroll
            for (int j = 0; j < OD2; j++) outv2[j] = mul2(outv2[j], rn2);
        }

        // ---- reconstruct + alpha: alpha = Σ_id xn[id]·(Σ_j outv[j]·w[id][j]) ----
        float alpha = 0.0f;
#pragma unroll
        for (int id = 0; id < ID; id++) {
            u64 acc = mul2(outv2[0], wq[id * OD2 + 0]);
#pragma unroll
            for (int j = 1; j < OD2; j++)
                acc = fma2(outv2[j], wq[id * OD2 + j], acc);
            float2 rf = upk2(acc);
            alpha = fmaf(rf.x + rf.y, xn[id], alpha);
        }

        alpha_s[b][oc] = alpha;
        __syncthreads();   // alpha visible; all w_s/x_s reads complete

        // ---- alpha normalization, then flush this ic's contribution ----
        float asum = 0.0f;
#pragma unroll
        for (int o2 = 0; o2 < OC; o2++) asum += alpha_s[b][o2];
        float an = alpha * __fdividef(1.0f, asum + EPSV);
        u64 an2 = pk2(an, an);
#pragma unroll
        for (int j = 0; j < OD2; j++) {
            float2 f = upk2(mul2(outv2[j], an2));
            atomicAdd(&out[(b * OC + oc) * OD + 2 * j],     f.x);
            atomicAdd(&out[(b * OC + oc) * OD + 2 * j + 1], f.y);
        }

        // ---- reload next slab (w_s/x_s free: sync above ended all reads) ----
        if (k + 1 < ICPB) {
            const int icn = blockIdx.x * ICPB + k + 1;
            for (int i = tid; i < WSLAB; i += NTHREADS)
                w_s[i] = w[icn * WSLAB + i];
            if (tid < BATCH * ID) {
                int bb = tid >> 3, id = tid & 7;
                x_s[bb][id] = x[(bb * IC + icn) * ID + id];
            }
            __syncthreads();   // new slab + alpha_s reads complete
        }
    }
}

extern "C" void kernel_launch(void* const* d_in, const int* in_sizes, int n_in,
                              void* d_out, int out_size) {
    const float* x = (const float*)d_in[0];   // [32, 1152, 8]
    const float* w = (const float*)d_in[1];   // [1152, 10, 8, 16]
    float* out = (float*)d_out;               // [32, 10, 16]

    zero_out_kernel<<<(BATCH * OC * OD + 255) / 256, 256>>>(out, BATCH * OC * OD);
    caps_kernel<<<IC / ICPB, NTHREADS>>>(x, w, out);
}

// round 8
// speedup vs baseline: 2.5675x; 2.5675x over previous
#include <cuda_runtime.h>

#define IC 1152
#define OC 10
#define ID 8
#define OD 16
#define OD2 8          // packed f32x2 pairs
#define BATCH 32
#define NITER 5
#define EPSV 1e-20f
#define ICPB 4
#define NTHREADS 320   // 10 warps: warp = oc, lane = b
#define WSLAB (OC * ID * OD)   // 1280 floats per ic

typedef unsigned long long u64;

__device__ __forceinline__ u64 pk2(float lo, float hi) {
    u64 r; asm("mov.b64 %0, {%1,%2};" : "=l"(r) : "f"(lo), "f"(hi)); return r;
}
__device__ __forceinline__ float2 upk2(u64 v) {
    float2 f; asm("mov.b64 {%0,%1}, %2;" : "=f"(f.x), "=f"(f.y) : "l"(v)); return f;
}
__device__ __forceinline__ u64 mul2(u64 a, u64 b) {
    u64 r; asm("mul.rn.f32x2 %0, %1, %2;" : "=l"(r) : "l"(a), "l"(b)); return r;
}
__device__ __forceinline__ u64 add2(u64 a, u64 b) {
    u64 r; asm("add.rn.f32x2 %0, %1, %2;" : "=l"(r) : "l"(a), "l"(b)); return r;
}
__device__ __forceinline__ u64 fma2(u64 a, u64 b, u64 c) {
    u64 r; asm("fma.rn.f32x2 %0, %1, %2, %3;" : "=l"(r) : "l"(a), "l"(b), "l"(c)); return r;
}

__global__ void zero_out_kernel(float* out, int n) {
    int i = blockIdx.x * blockDim.x + threadIdx.x;
    if (i < n) out[i] = 0.0f;
}

__global__ __launch_bounds__(NTHREADS, 1)   // 1 CTA/SM: lift the 96-reg cap, kill spills
void caps_kernel(const float* __restrict__ x,
                 const float* __restrict__ w,
                 float* __restrict__ out) {
    __shared__ __align__(16) float w_s[WSLAB];      // current ic weight slab
    __shared__ float x_s[BATCH][ID + 1];            // padded: stride 9
    __shared__ float alpha_s[BATCH][OC];

    const int tid = threadIdx.x;
    const int b   = tid & 31;     // lane
    const int oc  = tid >> 5;     // warp

    u64 res2[OD2];
#pragma unroll
    for (int j = 0; j < OD2; j++) res2[j] = 0ull;

    // ---- load slab 0 ----
    {
        const int ic0 = blockIdx.x * ICPB;
        for (int i = tid; i < WSLAB; i += NTHREADS)
            w_s[i] = w[ic0 * WSLAB + i];
        if (tid < BATCH * ID) {
            int bb = tid >> 3, id = tid & 7;
            x_s[bb][id] = x[(bb * IC + ic0) * ID + id];
        }
    }
    __syncthreads();

    for (int k = 0; k < ICPB; k++) {
        const int ic = blockIdx.x * ICPB + k;

        // ---- register-prefetch next slab (hidden behind compute) ----
        float wpre0 = 0.f, wpre1 = 0.f, wpre2 = 0.f, wpre3 = 0.f, xpre = 0.f;
        if (k + 1 < ICPB) {
            const float* wn = w + (ic + 1) * WSLAB;
            wpre0 = wn[tid];
            wpre1 = wn[tid + NTHREADS];
            wpre2 = wn[tid + 2 * NTHREADS];
            wpre3 = wn[tid + 3 * NTHREADS];
            if (tid < BATCH * ID)
                xpre = x[((tid >> 3) * IC + ic + 1) * ID + (tid & 7)];
        }

        // ---- normalize x over ID ----
        float xn[ID];
        float xs = 0.0f;
#pragma unroll
        for (int id = 0; id < ID; id++) { xn[id] = x_s[b][id]; xs += xn[id]; }
        float xr = __fdividef(1.0f, xs + EPSV);
#pragma unroll
        for (int id = 0; id < ID; id++) xn[id] *= xr;

        const u64* wq = reinterpret_cast<const u64*>(w_s + oc * ID * OD);

        // ---- NNMF, factored form:
        //   d[id] = Σ_j outv[j]·w[id][j]      8 independent packed-dot chains
        //   s[id] = xn[id] / (d[id]+ε)        8 overlapping MUFU rcps
        //   t[j] += s[id]·w[id][j]            8 independent column chains
        //   outv[j] *= t[j]
        // per-iteration normalization is scale-invariant; applied once ----
        u64 outv2[OD2];
#pragma unroll
        for (int j = 0; j < OD2; j++) outv2[j] = pk2(1.0f / OD, 1.0f / OD);

#pragma unroll
        for (int it = 0; it < NITER; it++) {
            // phase 1: dots, scalar results
            float s[ID];
#pragma unroll
            for (int id = 0; id < ID; id++) {
                u64 acc = mul2(outv2[0], wq[id * OD2 + 0]);
#pragma unroll
                for (int j = 1; j < OD2; j++)
                    acc = fma2(outv2[j], wq[id * OD2 + j], acc);
                float2 f = upk2(acc);
                s[id] = f.x + f.y;
            }
            // phase 2: batched reciprocals
#pragma unroll
            for (int id = 0; id < ID; id++)
                s[id] = __fdividef(xn[id], s[id] + EPSV);
            // phase 3: column accumulation, 8 independent chains
            u64 t[OD2];
            {
                u64 sp = pk2(s[0], s[0]);
#pragma unroll
                for (int j = 0; j < OD2; j++) t[j] = mul2(sp, wq[j]);
            }
#pragma unroll
            for (int id = 1; id < ID; id++) {
                u64 sp = pk2(s[id], s[id]);
#pragma unroll
                for (int j = 0; j < OD2; j++)
                    t[j] = fma2(sp, wq[id * OD2 + j], t[j]);
            }
#pragma unroll
            for (int j = 0; j < OD2; j++)
                outv2[j] = mul2(outv2[j], t[j]);
        }

        // ---- final normalization over OD (needed before alpha mixes oc) ----
        {
            u64 t01 = add2(outv2[0], outv2[1]), t23 = add2(outv2[2], outv2[3]);
            u64 t45 = add2(outv2[4], outv2[5]), t67 = add2(outv2[6], outv2[7]);
            float2 tf = upk2(add2(add2(t01, t23), add2(t45, t67)));
            float rn = __fdividef(1.0f, tf.x + tf.y + EPSV);
            u64 rn2 = pk2(rn, rn);
#pragma unroll
            for (int j = 0; j < OD2; j++) outv2[j] = mul2(outv2[j], rn2);
        }

        // ---- reconstruct + alpha: alpha = Σ_id xn[id]·(Σ_j outv[j]·w[id][j]) ----
        float alpha = 0.0f;
#pragma unroll
        for (int id = 0; id < ID; id++) {
            u64 acc = mul2(outv2[0], wq[id * OD2 + 0]);
#pragma unroll
            for (int j = 1; j < OD2; j++)
                acc = fma2(outv2[j], wq[id * OD2 + j], acc);
            float2 rf = upk2(acc);
            alpha = fmaf(rf.x + rf.y, xn[id], alpha);
        }

        alpha_s[b][oc] = alpha;
        __syncthreads();   // alpha visible; all w_s/x_s reads complete

        // ---- store prefetched slab (w_s/x_s no longer read this k) ----
        if (k + 1 < ICPB) {
            w_s[tid]                = wpre0;
            w_s[tid + NTHREADS]     = wpre1;
            w_s[tid + 2 * NTHREADS] = wpre2;
            w_s[tid + 3 * NTHREADS] = wpre3;
            if (tid < BATCH * ID)
                x_s[tid >> 3][tid & 7] = xpre;
        }

        float asum = 0.0f;
#pragma unroll
        for (int o2 = 0; o2 < OC; o2++) asum += alpha_s[b][o2];
        float an = alpha * __fdividef(1.0f, asum + EPSV);
        u64 an2 = pk2(an, an);
#pragma unroll
        for (int j = 0; j < OD2; j++)
            res2[j] = fma2(outv2[j], an2, res2[j]);

        __syncthreads();   // new slab visible + alpha_s reads complete
    }

    // ---- accumulate over ic (288 adds per address — cheap) ----
#pragma unroll
    for (int j = 0; j < OD2; j++) {
        float2 f = upk2(res2[j]);
        atomicAdd(&out[(b * OC + oc) * OD + 2 * j],     f.x);
        atomicAdd(&out[(b * OC + oc) * OD + 2 * j + 1], f.y);
    }
}

extern "C" void kernel_launch(void* const* d_in, const int* in_sizes, int n_in,
                              void* d_out, int out_size) {
    const float* x = (const float*)d_in[0];   // [32, 1152, 8]
    const float* w = (const float*)d_in[1];   // [1152, 10, 8, 16]
    float* out = (float*)d_out;               // [32, 10, 16]

    zero_out_kernel<<<(BATCH * OC * OD + 255) / 256, 256>>>(out, BATCH * OC * OD);
    caps_kernel<<<IC / ICPB, NTHREADS>>>(x, w, out);
}